// round 9
// baseline (speedup 1.0000x reference)
#include <cuda_runtime.h>
#include <cuda_bf16.h>

// ALiBi: out[b,h,i,j] = scores[b,h,i,j] + (j - i) * slopes[h]
// B=2, H=16, S=2048. Pure HBM streaming: 512 MiB in + 512 MiB out.
//
// FINAL (converged at the memory-system ceiling, 6.85 TB/s = 85.6% of spec):
// achieved bandwidth proved invariant to MLP (4 vs 8), occupancy (39-79%),
// grid shape (dense vs persistent), and block size (256 vs 512). Traffic is
// irreducible (fp32 in/out, zero reuse); compute pipes <10% busy. Remaining
// gap to 8 TB/s spec is DRAM read/write turnaround, not software-addressable.
//
// Config: 256-thread blocks, 2 rows/block, 128 lanes/row, 4 independent
// front-batched float4 loads per thread (MLP_p1=4), streaming cache hints.

static constexpr int S = 2048;
static constexpr int H = 16;
static constexpr int THREADS = 256;
static constexpr int ROWS_PER_BLOCK = 2;      // 256 threads / 128 lanes-per-row
static constexpr int LANES_PER_ROW = 128;
static constexpr int UNROLL = 4;              // float4s per thread (one row = 128*4 float4)

__global__ void __launch_bounds__(THREADS, 8)
alibi_kernel(const float* __restrict__ scores,
             const float* __restrict__ slopes,
             float* __restrict__ out)
{
    const int tid  = threadIdx.x;
    const int lane = tid & (LANES_PER_ROW - 1);       // 0..127
    const int rib  = tid >> 7;                        // row within block, 0..1

    const unsigned row = blockIdx.x * ROWS_PER_BLOCK + rib;
    const int i = row & (S - 1);
    const int h = (row >> 11) & (H - 1);
    const float slope = __ldg(&slopes[h]);

    // This thread's 4 float4s: columns j0 + k*512 floats (k=0..3), same row.
    const int j0 = lane * 4;
    const size_t base = (size_t)row * S + j0;

    const float4* __restrict__ src = reinterpret_cast<const float4*>(scores + base);
    float4*       __restrict__ dst = reinterpret_cast<float4*>(out + base);

    // Front-batch all 4 independent loads -> 4 outstanding DRAM requests
    float4 v[UNROLL];
#pragma unroll
    for (int k = 0; k < UNROLL; k++)
        v[k] = __ldcs(src + k * LANES_PER_ROW);       // stride 128 float4 = 512 floats

    // bias = (j - i) * slope
#pragma unroll
    for (int k = 0; k < UNROLL; k++) {
        const float d0 = (float)(j0 + k * (LANES_PER_ROW * 4) - i);
        v[k].x = fmaf(d0,        slope, v[k].x);
        v[k].y = fmaf(d0 + 1.0f, slope, v[k].y);
        v[k].z = fmaf(d0 + 2.0f, slope, v[k].z);
        v[k].w = fmaf(d0 + 3.0f, slope, v[k].w);
    }

#pragma unroll
    for (int k = 0; k < UNROLL; k++)
        __stcs(dst + k * LANES_PER_ROW, v[k]);
}

extern "C" void kernel_launch(void* const* d_in, const int* in_sizes, int n_in,
                              void* d_out, int out_size)
{
    const float* scores = (const float*)d_in[0];
    const float* slopes = (const float*)d_in[1];
    float* out = (float*)d_out;

    const long long total = (long long)out_size;          // B*H*S*S
    const int rows = (int)(total / S);                    // 65536
    const int blocks = rows / ROWS_PER_BLOCK;             // 32768

    alibi_kernel<<<blocks, THREADS>>>(scores, slopes, out);
}